// round 13
// baseline (speedup 1.0000x reference)
#include <cuda_runtime.h>
#include <cuda_fp16.h>
#include <cstdint>

#define DEV_INLINE __device__ __forceinline__

// ---------------------------------------------------------------------------
// out[16384,4096] = x[16384,1024] @ (W + w1[s]@w2[t])^T + bias
//
// Single fp16 GEMM (validated: rel_err 2.935e-4 vs 1e-3 threshold).
//
// R11 post-mortem: halving SMEM traffic changed nothing -> smem not binding.
// Invariant binder across R8/R10/R11: L2 delivery. 128x128 tiles demand
// 32 B/cyc/SM of cp.async data vs ~41 B/cyc/SM LTS cap (77%) -> ~71% tensor
// plateau. R12: 256x128 CTA tile cuts L2 volume 2GB -> 1.5GB (25%):
//   - 256 threads, 8 warps = 4M x 2N of the SAME 64x64 warp tile as R11
//     (per-warp regs unchanged ~210; 256thr x 210 = 53.8K < 64K RF).
//   - 1 CTA/SM, STAGES=4 (48KB/stage, 192KB smem) for deeper prefetch.
//   - L2 demand 24 B/cyc/SM (58% of cap).
//
// NOTE: tcgen05 unavailable (harness PTX targets base sm_103, no 'a');
// arch-neutral mma.sync (HMMA) + ldmatrix + cp.async.
// ---------------------------------------------------------------------------
constexpr int Mdim = 16384;
constexpr int Ndim = 4096;
constexpr int Kdim = 1024;
constexpr int RANKC = 32;
constexpr int NLANG_OUT = 4096;

constexpr int BM = 256, BN = 128, BK = 64;
constexpr int KT = Kdim / BK;          // 16 k-stages per tile
constexpr int STAGES = 4;
constexpr int ROW_BYTES = BK * 2;      // 128 B per tile row
constexpr int A_TILE_BYTES = BM * ROW_BYTES;     // 32 KB
constexpr int B_TILE_BYTES = BN * ROW_BYTES;     // 16 KB
constexpr int STAGE_BYTES = A_TILE_BYTES + B_TILE_BYTES;  // 48 KB
constexpr int SMEM_BYTES = STAGES * STAGE_BYTES; // 192 KB
constexpr int THREADS = 256;           // 8 warps: 4M x 2N, warp tile 64x64

// Scratch (no cudaMalloc allowed): fp16 copies of x and w_eff
__device__ __half g_a[(size_t)Mdim * Kdim];   // 32 MB
__device__ __half g_b[(size_t)Ndim * Kdim];   // 8 MB

// ---------------------------------------------------------------------------
// helpers
// ---------------------------------------------------------------------------
DEV_INLINE uint32_t smem_to_u32(const void* p) {
    uint32_t a;
    asm("{ .reg .u64 t; cvta.to.shared.u64 t, %1; cvt.u32.u64 %0, t; }" : "=r"(a) : "l"(p));
    return a;
}

DEV_INLINE void cp_async16(uint32_t dst, const void* src) {
    asm volatile("cp.async.cg.shared.global [%0], [%1], 16;" :: "r"(dst), "l"(src) : "memory");
}
DEV_INLINE void cp_commit() { asm volatile("cp.async.commit_group;" ::: "memory"); }
template <int N> DEV_INLINE void cp_wait() {
    asm volatile("cp.async.wait_group %0;" :: "n"(N) : "memory");
}

DEV_INLINE void ldsm_x4(uint32_t& r0, uint32_t& r1, uint32_t& r2, uint32_t& r3, uint32_t addr) {
    asm volatile("ldmatrix.sync.aligned.m8n8.x4.shared.b16 {%0,%1,%2,%3}, [%4];"
                 : "=r"(r0), "=r"(r1), "=r"(r2), "=r"(r3) : "r"(addr));
}

DEV_INLINE void mma_f16(float& c0, float& c1, float& c2, float& c3,
                        uint32_t a0, uint32_t a1, uint32_t a2, uint32_t a3,
                        uint32_t b0, uint32_t b1) {
    asm volatile(
        "mma.sync.aligned.m16n8k16.row.col.f32.f16.f16.f32 "
        "{%0,%1,%2,%3}, {%4,%5,%6,%7}, {%8,%9}, {%0,%1,%2,%3};"
        : "+f"(c0), "+f"(c1), "+f"(c2), "+f"(c3)
        : "r"(a0), "r"(a1), "r"(a2), "r"(a3), "r"(b0), "r"(b1));
}

// Full 128B-row XOR swizzle on 16B chunks: 8 chunks/row, phys = c ^ (row & 7).
DEV_INLINE uint32_t swz(int row, int chunk) {
    return (uint32_t)(row * ROW_BYTES + ((chunk ^ (row & 7)) << 4));
}

// ---------------------------------------------------------------------------
// Fused prep: blocks [0,1024) build w_eff fp16 (4 rows each);
//             blocks [1024, 1024+16384) cast x.
// ---------------------------------------------------------------------------
constexpr int WROWS = 4;
constexpr int WBLKS = Ndim / WROWS;            // 1024

__global__ void prep_kernel(const float4* __restrict__ x4,
                            const float* __restrict__ weight,
                            const float* __restrict__ w1,
                            const float* __restrict__ w2,
                            const int* __restrict__ src_id,
                            const int* __restrict__ tgt_id) {
    const int tid = threadIdx.x;
    if (blockIdx.x < (unsigned)WBLKS) {
        __shared__ float a[WROWS][RANKC];
        const int o0 = blockIdx.x * WROWS;
        if (tid < WROWS * RANKC)
            a[tid >> 5][tid & 31] =
                w1[((size_t)src_id[0] * NLANG_OUT + o0 + (tid >> 5)) * RANKC + (tid & 31)];
        __syncthreads();
        const int t = tgt_id[0];

        const int i0 = tid * 4;   // 256 threads * 4 = 1024 columns
        float4 acc[WROWS];
#pragma unroll
        for (int w = 0; w < WROWS; ++w)
            acc[w] = *reinterpret_cast<const float4*>(weight + (size_t)(o0 + w) * Kdim + i0);
#pragma unroll
        for (int r = 0; r < RANKC; ++r) {
            const float4 b = *reinterpret_cast<const float4*>(w2 + ((size_t)t * RANKC + r) * Kdim + i0);
#pragma unroll
            for (int w = 0; w < WROWS; ++w) {
                const float ar = a[w][r];
                acc[w].x = fmaf(ar, b.x, acc[w].x);
                acc[w].y = fmaf(ar, b.y, acc[w].y);
                acc[w].z = fmaf(ar, b.z, acc[w].z);
                acc[w].w = fmaf(ar, b.w, acc[w].w);
            }
        }
#pragma unroll
        for (int w = 0; w < WROWS; ++w) {
            __half2* p = reinterpret_cast<__half2*>(g_b + (size_t)(o0 + w) * Kdim + i0);
            p[0] = __floats2half2_rn(acc[w].x, acc[w].y);
            p[1] = __floats2half2_rn(acc[w].z, acc[w].w);
        }
    } else {
        const size_t i = (size_t)(blockIdx.x - WBLKS) * blockDim.x + tid;  // < M*K/4
        const float4 v = x4[i];
        __half2* p = reinterpret_cast<__half2*>(g_a + 4 * i);
        p[0] = __floats2half2_rn(v.x, v.y);
        p[1] = __floats2half2_rn(v.z, v.w);
    }
}

// ---------------------------------------------------------------------------
// GEMM: 256x128 CTA tile, 8 warps (4M x 2N), warp tile 64x64, BK=64,
// 4-stage cp.async pipeline (48KB/stage), 1 CTA/SM.
// ---------------------------------------------------------------------------
__global__ void __launch_bounds__(THREADS, 1)
gemm_kernel(float* __restrict__ out, const float* __restrict__ bias) {
    extern __shared__ char smem[];
    const uint32_t smem_base = smem_to_u32(smem);
    const int tid  = threadIdx.x;
    const int lane = tid & 31;
    const int wid  = tid >> 5;
    const int warp_m = wid & 3;     // 4 warps in M -> 64 rows each
    const int warp_n = wid >> 2;    // 2 warps in N -> 64 cols each
    const int n0 = blockIdx.x * BN; // n fastest: A-panel reuse in L2
    const int m0 = blockIdx.y * BM;

    // ---- cp.async mapping ----
    // A: 2048 chunks (256 rows x 8), 8 per thread: row = row0 + 32j
    // B: 1024 chunks (128 rows x 8), 4 per thread: row = row0 + 32j
    const int row0 = tid >> 3;          // 0..31
    const int ch0  = tid & 7;
    const uint32_t st0 = swz(row0, ch0);
    const __half* srcA0 = g_a + (size_t)(m0 + row0) * Kdim + ch0 * 8;
    const __half* srcB0 = g_b + (size_t)(n0 + row0) * Kdim + ch0 * 8;
    constexpr size_t JSTRIDE = (size_t)32 * Kdim;   // +32 rows per j
    constexpr uint32_t JSMEM = 32 * ROW_BYTES;      // 4096 B

    // ---- ldmatrix smem offsets (constant across stages) ----
    const int g  = lane >> 3;
    const int lr = lane & 7;
    uint32_t offA0[4], offB0[4];
#pragma unroll
    for (int kk = 0; kk < 4; ++kk) {
        offA0[kk] = swz(warp_m * 64 + (g & 1) * 8 + lr, kk * 2 + (g >> 1));
        offB0[kk] = swz(warp_n * 64 + (g >> 1) * 8 + lr, kk * 2 + (g & 1));
    }

    float acc[4][8][4];
#pragma unroll
    for (int mt = 0; mt < 4; ++mt)
#pragma unroll
        for (int nt = 0; nt < 8; ++nt)
#pragma unroll
            for (int c = 0; c < 4; ++c) acc[mt][nt][c] = 0.f;

    // ---- prologue: stages 0..STAGES-2 ----
#pragma unroll
    for (int s = 0; s < STAGES - 1; ++s) {
        const uint32_t sa = smem_base + s * STAGE_BYTES;
        const uint32_t sb = sa + A_TILE_BYTES;
        const int k0 = s * BK;
#pragma unroll
        for (int j = 0; j < 8; ++j)
            cp_async16(sa + st0 + j * JSMEM, srcA0 + j * JSTRIDE + k0);
#pragma unroll
        for (int j = 0; j < 4; ++j)
            cp_async16(sb + st0 + j * JSMEM, srcB0 + j * JSTRIDE + k0);
        cp_commit();
    }

    // ---- mainloop: 16 stages ----
    int ld_stage = STAGES - 1;
    int cp_stage = 0;
#pragma unroll 1
    for (int s = 0; s < KT; ++s) {
        cp_wait<STAGES - 2>();
        __syncthreads();

        // prefetch stage s+STAGES-1
        if (s + STAGES - 1 < KT) {
            const uint32_t sa = smem_base + ld_stage * STAGE_BYTES;
            const uint32_t sb = sa + A_TILE_BYTES;
            const int k0 = (s + STAGES - 1) * BK;
#pragma unroll
            for (int j = 0; j < 8; ++j)
                cp_async16(sa + st0 + j * JSMEM, srcA0 + j * JSTRIDE + k0);
#pragma unroll
            for (int j = 0; j < 4; ++j)
                cp_async16(sb + st0 + j * JSMEM, srcB0 + j * JSTRIDE + k0);
        }
        cp_commit();   // fixed group count per iter
        if (++ld_stage == STAGES) ld_stage = 0;

        const uint32_t sa = smem_base + cp_stage * STAGE_BYTES;
        const uint32_t sb = sa + A_TILE_BYTES;
        if (++cp_stage == STAGES) cp_stage = 0;

#pragma unroll
        for (int kk = 0; kk < 4; ++kk) {
            uint32_t a[4][4];
#pragma unroll
            for (int mt = 0; mt < 4; ++mt)
                ldsm_x4(a[mt][0], a[mt][1], a[mt][2], a[mt][3],
                        sa + offA0[kk] + mt * 2048);
            uint32_t b[8][2];
#pragma unroll
            for (int np = 0; np < 4; ++np) {
                uint32_t r0, r1, r2, r3;
                ldsm_x4(r0, r1, r2, r3, sb + offB0[kk] + np * 2048);
                b[2 * np][0] = r0; b[2 * np][1] = r1;
                b[2 * np + 1][0] = r2; b[2 * np + 1][1] = r3;
            }
#pragma unroll
            for (int mt = 0; mt < 4; ++mt)
#pragma unroll
                for (int nt = 0; nt < 8; ++nt)
                    mma_f16(acc[mt][nt][0], acc[mt][nt][1], acc[mt][nt][2], acc[mt][nt][3],
                            a[mt][0], a[mt][1], a[mt][2], a[mt][3],
                            b[nt][0], b[nt][1]);
        }
    }

    // ---- epilogue ----
    const int qid = lane >> 2;     // row 0..7 within m8
    const int qln = lane & 3;      // col pair
    const int nbase = n0 + warp_n * 64;
    float2 bv[8];
#pragma unroll
    for (int nt = 0; nt < 8; ++nt)
        bv[nt] = *reinterpret_cast<const float2*>(bias + nbase + nt * 8 + qln * 2);

#pragma unroll
    for (int mt = 0; mt < 4; ++mt) {
#pragma unroll
        for (int rr = 0; rr < 2; ++rr) {
            const int m = m0 + warp_m * 64 + mt * 16 + rr * 8 + qid;
            float* orow = out + (size_t)m * Ndim + nbase;
#pragma unroll
            for (int nt = 0; nt < 8; ++nt) {
                float2 v;
                v.x = acc[mt][nt][rr * 2 + 0] + bv[nt].x;
                v.y = acc[mt][nt][rr * 2 + 1] + bv[nt].y;
                *reinterpret_cast<float2*>(orow + nt * 8 + qln * 2) = v;
            }
        }
    }
}

// ---------------------------------------------------------------------------
// Launch
// ---------------------------------------------------------------------------
extern "C" void kernel_launch(void* const* d_in, const int* in_sizes, int n_in,
                              void* d_out, int out_size) {
    const float* x      = (const float*)d_in[0];   // [4,4096,1024]
    const float* weight = (const float*)d_in[1];   // [4096,1024]
    const float* bias   = (const float*)d_in[2];   // [4096]
    const float* w1     = (const float*)d_in[3];   // [9,4096,32]
    const float* w2     = (const float*)d_in[4];   // [9,32,1024]
    const int*   src_id = (const int*)d_in[5];
    const int*   tgt_id = (const int*)d_in[6];
    float* out = (float*)d_out;
    (void)in_sizes; (void)n_in; (void)out_size;

    cudaFuncSetAttribute(gemm_kernel, cudaFuncAttributeMaxDynamicSharedMemorySize, SMEM_BYTES);

    prep_kernel<<<WBLKS + (Mdim * Kdim / 4) / 256, 256>>>(
        reinterpret_cast<const float4*>(x), weight, w1, w2, src_id, tgt_id);

    dim3 grid(Ndim / BN, Mdim / BM);   // (32, 64), n fastest
    gemm_kernel<<<grid, THREADS, SMEM_BYTES>>>(out, bias);
}

// round 15
// speedup vs baseline: 1.2556x; 1.2556x over previous
#include <cuda_runtime.h>
#include <cuda_fp16.h>
#include <cstdint>

#define DEV_INLINE __device__ __forceinline__

// ---------------------------------------------------------------------------
// out[16384,4096] = x[16384,1024] @ (W + w1[s]@w2[t])^T + bias
//
// Single fp16 GEMM (validated: rel_err 2.935e-4 vs 1e-3 threshold).
//
// R12 post-mortem: L2-BW hypothesis falsified (25% less traffic -> slower at
// 1 CTA/SM). Binder is the stage-boundary bubble: after each barrier all
// warps LDSM before any HMMA can issue (~600 cyc idle per stage-pair).
// R13: R11 shape (128 thr, 4 warps, 64x64 warp tiles, 128x128 CTA tile,
// BK=64, STAGES=3, 2 CTA/SM) + CUTLASS-style fragment double buffering:
//   - LDSM for chunk kk+1 issued BEFORE MMAs of chunk kk
//   - at stage boundary: prefetch/commit/wait/bar/LDSM(next stage kk0),
//     THEN the last MMA batch (operands already in regs) -> HMMA resumes
//     immediately after the barrier.
// Regs: acc 128 + frags 64 + addr ~= 242 <= 255 cap at (128,2).
//
// NOTE: tcgen05 unavailable (harness PTX targets base sm_103, no 'a');
// arch-neutral mma.sync (HMMA) + ldmatrix + cp.async.
// ---------------------------------------------------------------------------
constexpr int Mdim = 16384;
constexpr int Ndim = 4096;
constexpr int Kdim = 1024;
constexpr int RANKC = 32;
constexpr int NLANG_OUT = 4096;

constexpr int BM = 128, BN = 128, BK = 64;
constexpr int KT = Kdim / BK;        // 16 k-stages per tile
constexpr int STAGES = 3;
constexpr int ROW_BYTES = BK * 2;    // 128 B per tile row
constexpr int TILE_BYTES = BM * ROW_BYTES;       // 16 KB
constexpr int STAGE_BYTES = 2 * TILE_BYTES;      // A + B = 32 KB
constexpr int SMEM_BYTES = STAGES * STAGE_BYTES; // 96 KB
constexpr int THREADS = 128;         // 4 warps: 2M x 2N, warp tile 64x64

// Scratch (no cudaMalloc allowed): fp16 copies of x and w_eff
__device__ __half g_a[(size_t)Mdim * Kdim];   // 32 MB
__device__ __half g_b[(size_t)Ndim * Kdim];   // 8 MB

// ---------------------------------------------------------------------------
// helpers
// ---------------------------------------------------------------------------
DEV_INLINE uint32_t smem_to_u32(const void* p) {
    uint32_t a;
    asm("{ .reg .u64 t; cvta.to.shared.u64 t, %1; cvt.u32.u64 %0, t; }" : "=r"(a) : "l"(p));
    return a;
}

DEV_INLINE void cp_async16(uint32_t dst, const void* src) {
    asm volatile("cp.async.cg.shared.global [%0], [%1], 16;" :: "r"(dst), "l"(src) : "memory");
}
DEV_INLINE void cp_commit() { asm volatile("cp.async.commit_group;" ::: "memory"); }
template <int N> DEV_INLINE void cp_wait() {
    asm volatile("cp.async.wait_group %0;" :: "n"(N) : "memory");
}

DEV_INLINE void ldsm_x4(uint32_t& r0, uint32_t& r1, uint32_t& r2, uint32_t& r3, uint32_t addr) {
    asm volatile("ldmatrix.sync.aligned.m8n8.x4.shared.b16 {%0,%1,%2,%3}, [%4];"
                 : "=r"(r0), "=r"(r1), "=r"(r2), "=r"(r3) : "r"(addr));
}

DEV_INLINE void mma_f16(float& c0, float& c1, float& c2, float& c3,
                        uint32_t a0, uint32_t a1, uint32_t a2, uint32_t a3,
                        uint32_t b0, uint32_t b1) {
    asm volatile(
        "mma.sync.aligned.m16n8k16.row.col.f32.f16.f16.f32 "
        "{%0,%1,%2,%3}, {%4,%5,%6,%7}, {%8,%9}, {%0,%1,%2,%3};"
        : "+f"(c0), "+f"(c1), "+f"(c2), "+f"(c3)
        : "r"(a0), "r"(a1), "r"(a2), "r"(a3), "r"(b0), "r"(b1));
}

// Full 128B-row XOR swizzle on 16B chunks: 8 chunks/row, phys = c ^ (row & 7).
DEV_INLINE uint32_t swz(int row, int chunk) {
    return (uint32_t)(row * ROW_BYTES + ((chunk ^ (row & 7)) << 4));
}

// ---------------------------------------------------------------------------
// Fused prep: blocks [0,1024) build w_eff fp16 (4 rows each);
//             blocks [1024, 1024+16384) cast x.
// ---------------------------------------------------------------------------
constexpr int WROWS = 4;
constexpr int WBLKS = Ndim / WROWS;            // 1024

__global__ void prep_kernel(const float4* __restrict__ x4,
                            const float* __restrict__ weight,
                            const float* __restrict__ w1,
                            const float* __restrict__ w2,
                            const int* __restrict__ src_id,
                            const int* __restrict__ tgt_id) {
    const int tid = threadIdx.x;
    if (blockIdx.x < (unsigned)WBLKS) {
        __shared__ float a[WROWS][RANKC];
        const int o0 = blockIdx.x * WROWS;
        if (tid < WROWS * RANKC)
            a[tid >> 5][tid & 31] =
                w1[((size_t)src_id[0] * NLANG_OUT + o0 + (tid >> 5)) * RANKC + (tid & 31)];
        __syncthreads();
        const int t = tgt_id[0];

        const int i0 = tid * 4;   // 256 threads * 4 = 1024 columns
        float4 acc[WROWS];
#pragma unroll
        for (int w = 0; w < WROWS; ++w)
            acc[w] = *reinterpret_cast<const float4*>(weight + (size_t)(o0 + w) * Kdim + i0);
#pragma unroll
        for (int r = 0; r < RANKC; ++r) {
            const float4 b = *reinterpret_cast<const float4*>(w2 + ((size_t)t * RANKC + r) * Kdim + i0);
#pragma unroll
            for (int w = 0; w < WROWS; ++w) {
                const float ar = a[w][r];
                acc[w].x = fmaf(ar, b.x, acc[w].x);
                acc[w].y = fmaf(ar, b.y, acc[w].y);
                acc[w].z = fmaf(ar, b.z, acc[w].z);
                acc[w].w = fmaf(ar, b.w, acc[w].w);
            }
        }
#pragma unroll
        for (int w = 0; w < WROWS; ++w) {
            __half2* p = reinterpret_cast<__half2*>(g_b + (size_t)(o0 + w) * Kdim + i0);
            p[0] = __floats2half2_rn(acc[w].x, acc[w].y);
            p[1] = __floats2half2_rn(acc[w].z, acc[w].w);
        }
    } else {
        const size_t i = (size_t)(blockIdx.x - WBLKS) * blockDim.x + tid;  // < M*K/4
        const float4 v = x4[i];
        __half2* p = reinterpret_cast<__half2*>(g_a + 4 * i);
        p[0] = __floats2half2_rn(v.x, v.y);
        p[1] = __floats2half2_rn(v.z, v.w);
    }
}

// ---------------------------------------------------------------------------
// GEMM: 128x128 CTA tile, 4 warps (2M x 2N), warp tile 64x64, BK=64,
// 3-stage cp.async pipeline + register fragment double buffering, 2 CTA/SM.
// ---------------------------------------------------------------------------
__global__ void __launch_bounds__(THREADS, 2)
gemm_kernel(float* __restrict__ out, const float* __restrict__ bias) {
    extern __shared__ char smem[];
    const uint32_t smem_base = smem_to_u32(smem);
    const int tid  = threadIdx.x;
    const int lane = tid & 31;
    const int wid  = tid >> 5;
    const int warp_m = wid & 1;     // 2 warps in M -> 64 rows each
    const int warp_n = wid >> 1;    // 2 warps in N -> 64 cols each
    const int n0 = blockIdx.x * BN; // n fastest: W-panel reuse in L2
    const int m0 = blockIdx.y * BM;

    // ---- cp.async mapping: 8 chunks each for A and B per thread ----
    const int row0 = tid >> 3;          // 0..15
    const int ch0  = tid & 7;
    const uint32_t st0 = swz(row0, ch0);
    const __half* srcA0 = g_a + (size_t)(m0 + row0) * Kdim + ch0 * 8;
    const __half* srcB0 = g_b + (size_t)(n0 + row0) * Kdim + ch0 * 8;
    constexpr size_t JSTRIDE = (size_t)16 * Kdim;   // +16 rows per j
    constexpr uint32_t JSMEM = 16 * ROW_BYTES;      // 2048 B

    // ---- ldmatrix smem offsets (constant across stages) ----
    const int g  = lane >> 3;
    const int lr = lane & 7;
    uint32_t offA0[4], offB0[4];
#pragma unroll
    for (int kk = 0; kk < 4; ++kk) {
        offA0[kk] = swz(warp_m * 64 + (g & 1) * 8 + lr, kk * 2 + (g >> 1));
        offB0[kk] = swz(warp_n * 64 + (g >> 1) * 8 + lr, kk * 2 + (g & 1));
    }

    float acc[4][8][4];
#pragma unroll
    for (int mt = 0; mt < 4; ++mt)
#pragma unroll
        for (int nt = 0; nt < 8; ++nt)
#pragma unroll
            for (int c = 0; c < 4; ++c) acc[mt][nt][c] = 0.f;

    // ---- prologue: prefetch stages 0..1 ----
#pragma unroll
    for (int s = 0; s < STAGES - 1; ++s) {
        const uint32_t sa = smem_base + s * STAGE_BYTES;
        const uint32_t sb = sa + TILE_BYTES;
        const int k0 = s * BK;
#pragma unroll
        for (int j = 0; j < 8; ++j) {
            cp_async16(sa + st0 + j * JSMEM, srcA0 + j * JSTRIDE + k0);
            cp_async16(sb + st0 + j * JSMEM, srcB0 + j * JSTRIDE + k0);
        }
        cp_commit();
    }
    cp_wait<STAGES - 2>();   // stage 0 complete (stage 1 may be in flight)
    __syncthreads();

    // ---- fragment double buffers ----
    uint32_t afr[2][4][4];
    uint32_t bfr[2][8][2];

    // Load stage 0, kk=0 into buf 0.
    {
        const uint32_t sa = smem_base;
        const uint32_t sb = sa + TILE_BYTES;
#pragma unroll
        for (int mt = 0; mt < 4; ++mt)
            ldsm_x4(afr[0][mt][0], afr[0][mt][1], afr[0][mt][2], afr[0][mt][3],
                    sa + offA0[0] + mt * 2048);
#pragma unroll
        for (int np = 0; np < 4; ++np) {
            uint32_t r0, r1, r2, r3;
            ldsm_x4(r0, r1, r2, r3, sb + offB0[0] + np * 2048);
            bfr[0][2 * np][0] = r0; bfr[0][2 * np][1] = r1;
            bfr[0][2 * np + 1][0] = r2; bfr[0][2 * np + 1][1] = r3;
        }
    }

    // Rotating stage slot addresses: a0 = compute, a1 = next, a2 = prefetch tgt
    uint32_t slot0 = smem_base;
    uint32_t slot1 = smem_base + STAGE_BYTES;
    uint32_t slot2 = smem_base + 2 * STAGE_BYTES;

    // ---- mainloop ----
#pragma unroll 1
    for (int s = 0; s < KT; ++s) {
#pragma unroll
        for (int kk = 0; kk < 4; ++kk) {
            const int cb = kk & 1;        // current frag buffer
            const int nb = cb ^ 1;        // next frag buffer
            if (kk < 3) {
                // LDSM next chunk of current stage into the other buffer
                const uint32_t sa = slot0;
                const uint32_t sb = slot0 + TILE_BYTES;
#pragma unroll
                for (int mt = 0; mt < 4; ++mt)
                    ldsm_x4(afr[nb][mt][0], afr[nb][mt][1], afr[nb][mt][2], afr[nb][mt][3],
                            sa + offA0[kk + 1] + mt * 2048);
#pragma unroll
                for (int np = 0; np < 4; ++np) {
                    uint32_t r0, r1, r2, r3;
                    ldsm_x4(r0, r1, r2, r3, sb + offB0[kk + 1] + np * 2048);
                    bfr[nb][2 * np][0] = r0; bfr[nb][2 * np][1] = r1;
                    bfr[nb][2 * np + 1][0] = r2; bfr[nb][2 * np + 1][1] = r3;
                }
            } else {
                // Stage transition: prefetch s+2, wait for s+1, barrier,
                // then LDSM next stage kk=0. Final MMA batch below uses regs.
                if (s + STAGES - 1 < KT) {
                    const int k0 = (s + STAGES - 1) * BK;
                    const uint32_t sa = slot2;
                    const uint32_t sb = slot2 + TILE_BYTES;
#pragma unroll
                    for (int j = 0; j < 8; ++j) {
                        cp_async16(sa + st0 + j * JSMEM, srcA0 + j * JSTRIDE + k0);
                        cp_async16(sb + st0 + j * JSMEM, srcB0 + j * JSTRIDE + k0);
                    }
                }
                cp_commit();              // fixed group count per stage
                cp_wait<STAGES - 2>();    // stage s+1 data complete
                __syncthreads();          // visibility + slot0 release
                if (s + 1 < KT) {
                    const uint32_t sa = slot1;
                    const uint32_t sb = slot1 + TILE_BYTES;
#pragma unroll
                    for (int mt = 0; mt < 4; ++mt)
                        ldsm_x4(afr[nb][mt][0], afr[nb][mt][1], afr[nb][mt][2], afr[nb][mt][3],
                                sa + offA0[0] + mt * 2048);
#pragma unroll
                    for (int np = 0; np < 4; ++np) {
                        uint32_t r0, r1, r2, r3;
                        ldsm_x4(r0, r1, r2, r3, sb + offB0[0] + np * 2048);
                        bfr[nb][2 * np][0] = r0; bfr[nb][2 * np][1] = r1;
                        bfr[nb][2 * np + 1][0] = r2; bfr[nb][2 * np + 1][1] = r3;
                    }
                }
            }
            // MMA on current buffer (independent of the LDSMs just issued)
#pragma unroll
            for (int mt = 0; mt < 4; ++mt)
#pragma unroll
                for (int nt = 0; nt < 8; ++nt)
                    mma_f16(acc[mt][nt][0], acc[mt][nt][1], acc[mt][nt][2], acc[mt][nt][3],
                            afr[cb][mt][0], afr[cb][mt][1], afr[cb][mt][2], afr[cb][mt][3],
                            bfr[cb][nt][0], bfr[cb][nt][1]);
        }
        // rotate stage slots
        const uint32_t t0 = slot0;
        slot0 = slot1; slot1 = slot2; slot2 = t0;
    }

    // ---- epilogue ----
    const int qid = lane >> 2;     // row 0..7 within m8
    const int qln = lane & 3;      // col pair
    const int nbase = n0 + warp_n * 64;
    float2 bv[8];
#pragma unroll
    for (int nt = 0; nt < 8; ++nt)
        bv[nt] = *reinterpret_cast<const float2*>(bias + nbase + nt * 8 + qln * 2);

#pragma unroll
    for (int mt = 0; mt < 4; ++mt) {
#pragma unroll
        for (int rr = 0; rr < 2; ++rr) {
            const int m = m0 + warp_m * 64 + mt * 16 + rr * 8 + qid;
            float* orow = out + (size_t)m * Ndim + nbase;
#pragma unroll
            for (int nt = 0; nt < 8; ++nt) {
                float2 v;
                v.x = acc[mt][nt][rr * 2 + 0] + bv[nt].x;
                v.y = acc[mt][nt][rr * 2 + 1] + bv[nt].y;
                *reinterpret_cast<float2*>(orow + nt * 8 + qln * 2) = v;
            }
        }
    }
}

// ---------------------------------------------------------------------------
// Launch
// ---------------------------------------------------------------------------
extern "C" void kernel_launch(void* const* d_in, const int* in_sizes, int n_in,
                              void* d_out, int out_size) {
    const float* x      = (const float*)d_in[0];   // [4,4096,1024]
    const float* weight = (const float*)d_in[1];   // [4096,1024]
    const float* bias   = (const float*)d_in[2];   // [4096]
    const float* w1     = (const float*)d_in[3];   // [9,4096,32]
    const float* w2     = (const float*)d_in[4];   // [9,32,1024]
    const int*   src_id = (const int*)d_in[5];
    const int*   tgt_id = (const int*)d_in[6];
    float* out = (float*)d_out;
    (void)in_sizes; (void)n_in; (void)out_size;

    cudaFuncSetAttribute(gemm_kernel, cudaFuncAttributeMaxDynamicSharedMemorySize, SMEM_BYTES);

    prep_kernel<<<WBLKS + (Mdim * Kdim / 4) / 256, 256>>>(
        reinterpret_cast<const float4*>(x), weight, w1, w2, src_id, tgt_id);

    dim3 grid(Ndim / BN, Mdim / BM);   // (32, 128), n fastest
    gemm_kernel<<<grid, THREADS, SMEM_BYTES>>>(out, bias);
}